// round 5
// baseline (speedup 1.0000x reference)
#include <cuda_runtime.h>
#include <cstdint>

// ---------------------------------------------------------------------------
// GIN: out = (relu(gin2(relu(gin1(x))))) @ Wl + bl
//   gin(h) = relu((h + scatter_sum(h[src]->dst)) @ Wa + ba) @ Wb + bb
// N=50000 nodes, E=800000 edges, 128 -> (128,128) -> (256,256) -> 40.
// Edge index dtype (int32 vs int64) detected on-device; indices converted to
// clamped int32 once. Aggregation via device-built dst-CSR (int atomics only),
// then pure gather. No host symbol-address APIs (breaks graph capture).
// ---------------------------------------------------------------------------

#define MAXN 50000
#define MAXE 1000000

__device__ __align__(16) float g_agg [MAXN * 128];
__device__ __align__(16) float g_bufA[MAXN * 256];
__device__ __align__(16) float g_bufB[MAXN * 256];
__device__ int g_rowptr[MAXN + 1];
__device__ int g_cursor[MAXN];
__device__ int g_deg   [MAXN];
__device__ int g_srcs  [MAXE];
__device__ int g_src32 [MAXE];
__device__ int g_dst32 [MAXE];
__device__ int g_bsum  [256];
__device__ int g_is64;

__device__ __forceinline__ float* devbuf(int s) {
    if (s == 0) return g_agg;
    if (s == 1) return g_bufA;
    return g_bufB;
}

// ======================= edge-index dtype handling ==========================
// If data is int64 (little-endian, values < 2^31), every odd 32-bit word is a
// zero hi-half. If int32, odd words are random node ids -> OR != 0 w.h.p.
__global__ void detect_idx64(const unsigned int* __restrict__ w) {
    if (threadIdx.x == 0 && blockIdx.x == 0) {
        unsigned int o = 0;
        #pragma unroll 1
        for (int i = 1; i < 256; i += 2) o |= w[i];
        g_is64 = (o == 0) ? 1 : 0;
    }
}

// Emit clamped int32 src/dst arrays regardless of source width.
__global__ void convert_idx(const unsigned int* __restrict__ w, int E, int N) {
    const int e = blockIdx.x * blockDim.x + threadIdx.x;
    if (e >= E) return;
    int s, d;
    if (g_is64) {
        s = (int)w[2 * e];
        d = (int)w[2 * (E + e)];
    } else {
        s = (int)w[e];
        d = (int)w[E + e];
    }
    s = min(max(s, 0), N - 1);
    d = min(max(d, 0), N - 1);
    g_src32[e] = s;
    g_dst32[e] = d;
}

// ============================ CSR construction ==============================

__global__ void zero_deg(int N) {
    int i = blockIdx.x * blockDim.x + threadIdx.x;
    if (i < N) g_deg[i] = 0;
}

__global__ void hist_deg(int E) {
    int e = blockIdx.x * blockDim.x + threadIdx.x;
    if (e < E) atomicAdd(&g_deg[g_dst32[e]], 1);
}

// per-block exclusive scan (256 elems), emits block sums
__global__ void scan_block(int N) {
    __shared__ int s[256];
    const int t = threadIdx.x;
    const int i = blockIdx.x * 256 + t;
    const int v = (i < N) ? g_deg[i] : 0;
    s[t] = v;
    __syncthreads();
    #pragma unroll
    for (int off = 1; off < 256; off <<= 1) {
        int tmp = (t >= off) ? s[t - off] : 0;
        __syncthreads();
        s[t] += tmp;
        __syncthreads();
    }
    if (i < N) g_rowptr[i] = s[t] - v;          // exclusive
    if (t == 255) g_bsum[blockIdx.x] = s[255];  // inclusive block total
}

// single-block exclusive scan of block sums (B <= 256)
__global__ void scan_partials(int B) {
    __shared__ int s[256];
    const int t = threadIdx.x;
    const int v = (t < B) ? g_bsum[t] : 0;
    s[t] = v;
    __syncthreads();
    #pragma unroll
    for (int off = 1; off < 256; off <<= 1) {
        int tmp = (t >= off) ? s[t - off] : 0;
        __syncthreads();
        s[t] += tmp;
        __syncthreads();
    }
    if (t < B) g_bsum[t] = s[t] - v;
}

__global__ void scan_add(int N, int E) {
    int i = blockIdx.x * blockDim.x + threadIdx.x;
    if (i < N) {
        int r = g_rowptr[i] + g_bsum[blockIdx.x];
        g_rowptr[i] = r;
        g_cursor[i] = r;
    }
    if (i == N) g_rowptr[N] = E;
}

__global__ void fill_csr(int E) {
    int e = blockIdx.x * blockDim.x + threadIdx.x;
    if (e >= E) return;
    int p = atomicAdd(&g_cursor[g_dst32[e]], 1);
    g_srcs[p] = g_src32[e];
}

// ============================ GIN aggregation ===============================
// out[i] = h[i] + sum_{j in CSR(i)} h[srcs[j]]    (feature dim 128)
// One warp per node; lane l owns float4 chunk l. No float atomics.
__global__ void gin_aggregate(const float* __restrict__ h_ext,
                              int h_sel, int out_sel, int N) {
    const int warp = (blockIdx.x * blockDim.x + threadIdx.x) >> 5;
    if (warp >= N) return;
    const int lane = threadIdx.x & 31;

    const float* __restrict__ h = h_ext ? h_ext : devbuf(h_sel);
    float* __restrict__ out = devbuf(out_sel);

    const float4* __restrict__ hp = reinterpret_cast<const float4*>(h);
    float4 acc = hp[warp * 32 + lane];          // self term
    const int beg = g_rowptr[warp];
    const int end = g_rowptr[warp + 1];
    for (int j = beg; j < end; j++) {
        const int s = g_srcs[j];                // broadcast load
        const float4 v = hp[s * 32 + lane];
        acc.x += v.x; acc.y += v.y; acc.z += v.z; acc.w += v.w;
    }
    reinterpret_cast<float4*>(out)[warp * 32 + lane] = acc;
}

// ================================ SGEMM =====================================
// C[M,N] = epilogue(A[M,K] @ W[K,N] + bias); BM=64 BN=128 BK=16, 256 thr,
// 4x8 per-thread tile, plain fp32 fmaf.
template<bool RELU>
__global__ void __launch_bounds__(256)
sgemm_bias(int a_sel, const float* __restrict__ W,
           const float* __restrict__ bias,
           int c_sel, float* __restrict__ c_ext,
           int M, int N, int K)
{
    constexpr int BM = 64, BN = 128, BK = 16;
    __shared__ __align__(16) float As[BK][BM + 4];   // As[k][m]
    __shared__ __align__(16) float Ws[BK][BN + 4];   // Ws[k][n]

    const float* __restrict__ A = devbuf(a_sel);
    float* __restrict__ C = (c_sel < 0) ? c_ext : devbuf(c_sel);

    const int tid  = threadIdx.x;
    const int tx   = tid & 15;    // cols tx*8 .. tx*8+7
    const int ty   = tid >> 4;    // rows ty*4 .. ty*4+3
    const int row0 = blockIdx.y * BM;
    const int col0 = blockIdx.x * BN;

    const int a_row = tid >> 2;
    const int a_col = (tid & 3) * 4;
    const int w_row = tid >> 5;
    const int w_col = (tid & 31) * 4;

    float acc[4][8];
    #pragma unroll
    for (int i = 0; i < 4; i++)
        #pragma unroll
        for (int j = 0; j < 8; j++) acc[i][j] = 0.f;

    const int  gr   = row0 + a_row;
    const bool a_ok = (gr < M);
    const int  gc   = col0 + w_col;
    const bool w_ok = (gc < N);

    for (int k0 = 0; k0 < K; k0 += BK) {
        float4 av = make_float4(0.f, 0.f, 0.f, 0.f);
        if (a_ok) av = *reinterpret_cast<const float4*>(A + (size_t)gr * K + k0 + a_col);
        As[a_col + 0][a_row] = av.x;
        As[a_col + 1][a_row] = av.y;
        As[a_col + 2][a_row] = av.z;
        As[a_col + 3][a_row] = av.w;
        #pragma unroll
        for (int r = 0; r < 2; r++) {
            const int wk = w_row + r * 8;
            float4 wv = make_float4(0.f, 0.f, 0.f, 0.f);
            if (w_ok) wv = *reinterpret_cast<const float4*>(W + (size_t)(k0 + wk) * N + gc);
            *reinterpret_cast<float4*>(&Ws[wk][w_col]) = wv;
        }
        __syncthreads();

        #pragma unroll
        for (int k = 0; k < BK; k++) {
            const float4 af = *reinterpret_cast<const float4*>(&As[k][ty * 4]);
            const float4 w0 = *reinterpret_cast<const float4*>(&Ws[k][tx * 8]);
            const float4 w1 = *reinterpret_cast<const float4*>(&Ws[k][tx * 8 + 4]);
            const float a4[4] = {af.x, af.y, af.z, af.w};
            const float w8[8] = {w0.x, w0.y, w0.z, w0.w, w1.x, w1.y, w1.z, w1.w};
            #pragma unroll
            for (int i = 0; i < 4; i++)
                #pragma unroll
                for (int j = 0; j < 8; j++)
                    acc[i][j] = fmaf(a4[i], w8[j], acc[i][j]);
        }
        __syncthreads();
    }

    #pragma unroll
    for (int i = 0; i < 4; i++) {
        const int r = row0 + ty * 4 + i;
        if (r >= M) continue;
        #pragma unroll
        for (int j = 0; j < 8; j++) {
            const int n0 = col0 + tx * 8 + j;
            if (n0 < N) {
                float v = acc[i][j] + bias[n0];
                if (RELU) v = fmaxf(v, 0.f);
                C[(size_t)r * N + n0] = v;
            }
        }
    }
}

// =============================== launch =====================================
extern "C" void kernel_launch(void* const* d_in, const int* in_sizes, int n_in,
                              void* d_out, int out_size)
{
    const float* x  = (const float*)d_in[0];
    const unsigned int* ei = (const unsigned int*)d_in[1];  // int32 OR int64 words
    const float* W1 = (const float*)d_in[2];
    const float* b1 = (const float*)d_in[3];
    const float* W2 = (const float*)d_in[4];
    const float* b2 = (const float*)d_in[5];
    const float* W3 = (const float*)d_in[6];
    const float* b3 = (const float*)d_in[7];
    const float* W4 = (const float*)d_in[8];
    const float* b4 = (const float*)d_in[9];
    const float* Wl = (const float*)d_in[10];
    const float* bl = (const float*)d_in[11];
    float* out = (float*)d_out;

    const int M = in_sizes[0] / 128;   // 50000 nodes
    const int E = in_sizes[1] / 2;     // 800000 edges
    const dim3 blk(256);
    const int nB   = (M + 255) / 256;
    const int eB   = (E + 255) / 256;
    const int aggB = (M * 32 + 255) / 256;     // one warp per node

    // ---- edge index normalize + CSR build (shared by both layers) ----
    detect_idx64 <<<1,  32 >>>(ei);
    convert_idx  <<<eB, blk>>>(ei, E, M);
    zero_deg     <<<nB, blk>>>(M);
    hist_deg     <<<eB, blk>>>(E);
    scan_block   <<<nB, blk>>>(M);
    scan_partials<<<1,  blk>>>(nB);
    scan_add     <<<nB, blk>>>(M, E);
    fill_csr     <<<eB, blk>>>(E);

    auto ggrid = [&](int n) { return dim3((n + 127) / 128, (M + 63) / 64); };

    // buffer ids: 0 = agg, 1 = bufA, 2 = bufB, -1 = external
    // ---- layer 1 ----
    gin_aggregate<<<aggB, blk>>>(x, 0, 0, M);
    sgemm_bias<true ><<<ggrid(128), blk>>>(0, W1, b1, 1, nullptr, M, 128, 128);
    sgemm_bias<true ><<<ggrid(128), blk>>>(1, W2, b2, 2, nullptr, M, 128, 128);

    // ---- layer 2 ----
    gin_aggregate<<<aggB, blk>>>(nullptr, 2, 0, M);
    sgemm_bias<true ><<<ggrid(256), blk>>>(0, W3, b3, 1, nullptr, M, 256, 128);
    sgemm_bias<true ><<<ggrid(256), blk>>>(1, W4, b4, 2, nullptr, M, 256, 256);

    // ---- head ----
    sgemm_bias<false><<<ggrid(40),  blk>>>(2, Wl, bl, -1, out, M, 40, 256);
}

// round 6
// speedup vs baseline: 1.0203x; 1.0203x over previous
#include <cuda_runtime.h>
#include <cstdint>

// ---------------------------------------------------------------------------
// GIN: out = (relu(gin2(relu(gin1(x))))) @ Wl + bl
//   gin(h) = relu((h + scatter_sum(h[src]->dst)) @ Wa + ba) @ Wb + bb
// N=50000 nodes, E=800000 edges, 128 -> (128,128) -> (256,256) -> 40.
// Edge indices (int32, detected) converted+clamped once; dst-CSR built with
// int atomics; aggregation is a pure gather. GEMM inner loop uses packed
// fma.rn.f32x2 (2 fp32 FMAs per issue slot).
// ---------------------------------------------------------------------------

#define MAXN 50000
#define MAXE 1000000

__device__ __align__(16) float g_agg [MAXN * 128];
__device__ __align__(16) float g_bufA[MAXN * 256];
__device__ __align__(16) float g_bufB[MAXN * 256];
__device__ int g_rowptr[MAXN + 1];
__device__ int g_cursor[MAXN];
__device__ int g_deg   [MAXN];
__device__ int g_srcs  [MAXE];
__device__ int g_src32 [MAXE];
__device__ int g_dst32 [MAXE];
__device__ int g_bsum  [256];
__device__ int g_is64;

__device__ __forceinline__ float* devbuf(int s) {
    if (s == 0) return g_agg;
    if (s == 1) return g_bufA;
    return g_bufB;
}

// ---- packed f32x2 helpers (FFMA2 is PTX-only; ptxas won't auto-fuse) -------
__device__ __forceinline__ unsigned long long pack2(float a) {
    unsigned long long r;
    asm("mov.b64 %0, {%1, %1};" : "=l"(r) : "f"(a));
    return r;
}
__device__ __forceinline__ void fma2(unsigned long long& d,
                                     unsigned long long a,
                                     unsigned long long b) {
    asm("fma.rn.f32x2 %0, %1, %2, %3;" : "=l"(d) : "l"(a), "l"(b), "l"(d));
}
__device__ __forceinline__ float2 unpack2(unsigned long long v) {
    float2 f;
    asm("mov.b64 {%0, %1}, %2;" : "=f"(f.x), "=f"(f.y) : "l"(v));
    return f;
}

// ======================= edge-index dtype handling ==========================
__global__ void detect_idx64(const unsigned int* __restrict__ w) {
    if (threadIdx.x == 0 && blockIdx.x == 0) {
        unsigned int o = 0;
        #pragma unroll 1
        for (int i = 1; i < 256; i += 2) o |= w[i];
        g_is64 = (o == 0) ? 1 : 0;
    }
}

__global__ void convert_idx(const unsigned int* __restrict__ w, int E, int N) {
    const int e = blockIdx.x * blockDim.x + threadIdx.x;
    if (e >= E) return;
    int s, d;
    if (g_is64) {
        s = (int)w[2 * e];
        d = (int)w[2 * (E + e)];
    } else {
        s = (int)w[e];
        d = (int)w[E + e];
    }
    s = min(max(s, 0), N - 1);
    d = min(max(d, 0), N - 1);
    g_src32[e] = s;
    g_dst32[e] = d;
}

// ============================ CSR construction ==============================

__global__ void zero_deg(int N) {
    int i = blockIdx.x * blockDim.x + threadIdx.x;
    if (i < N) g_deg[i] = 0;
}

__global__ void hist_deg(int E) {
    int e = blockIdx.x * blockDim.x + threadIdx.x;
    if (e < E) atomicAdd(&g_deg[g_dst32[e]], 1);
}

__global__ void scan_block(int N) {
    __shared__ int s[256];
    const int t = threadIdx.x;
    const int i = blockIdx.x * 256 + t;
    const int v = (i < N) ? g_deg[i] : 0;
    s[t] = v;
    __syncthreads();
    #pragma unroll
    for (int off = 1; off < 256; off <<= 1) {
        int tmp = (t >= off) ? s[t - off] : 0;
        __syncthreads();
        s[t] += tmp;
        __syncthreads();
    }
    if (i < N) g_rowptr[i] = s[t] - v;
    if (t == 255) g_bsum[blockIdx.x] = s[255];
}

__global__ void scan_partials(int B) {
    __shared__ int s[256];
    const int t = threadIdx.x;
    const int v = (t < B) ? g_bsum[t] : 0;
    s[t] = v;
    __syncthreads();
    #pragma unroll
    for (int off = 1; off < 256; off <<= 1) {
        int tmp = (t >= off) ? s[t - off] : 0;
        __syncthreads();
        s[t] += tmp;
        __syncthreads();
    }
    if (t < B) g_bsum[t] = s[t] - v;
}

__global__ void scan_add(int N, int E) {
    int i = blockIdx.x * blockDim.x + threadIdx.x;
    if (i < N) {
        int r = g_rowptr[i] + g_bsum[blockIdx.x];
        g_rowptr[i] = r;
        g_cursor[i] = r;
    }
    if (i == N) g_rowptr[N] = E;
}

__global__ void fill_csr(int E) {
    int e = blockIdx.x * blockDim.x + threadIdx.x;
    if (e >= E) return;
    int p = atomicAdd(&g_cursor[g_dst32[e]], 1);
    g_srcs[p] = g_src32[e];
}

// ============================ GIN aggregation ===============================
__global__ void gin_aggregate(const float* __restrict__ h_ext,
                              int h_sel, int out_sel, int N) {
    const int warp = (blockIdx.x * blockDim.x + threadIdx.x) >> 5;
    if (warp >= N) return;
    const int lane = threadIdx.x & 31;

    const float* __restrict__ h = h_ext ? h_ext : devbuf(h_sel);
    float* __restrict__ out = devbuf(out_sel);

    const float4* __restrict__ hp = reinterpret_cast<const float4*>(h);
    float4 acc = hp[warp * 32 + lane];          // self term
    const int beg = g_rowptr[warp];
    const int end = g_rowptr[warp + 1];
    for (int j = beg; j < end; j++) {
        const int s = g_srcs[j];                // broadcast load
        const float4 v = hp[s * 32 + lane];
        acc.x += v.x; acc.y += v.y; acc.z += v.z; acc.w += v.w;
    }
    reinterpret_cast<float4*>(out)[warp * 32 + lane] = acc;
}

// ================================ SGEMM =====================================
// C[M,N] = epilogue(A[M,K] @ W[K,N] + bias); BM=64 BN=128 BK=16, 256 thr,
// 4x8 per-thread tile held as 4x4 f32x2 accumulators (fma.rn.f32x2).
template<bool RELU>
__global__ void __launch_bounds__(256)
sgemm_bias(int a_sel, const float* __restrict__ W,
           const float* __restrict__ bias,
           int c_sel, float* __restrict__ c_ext,
           int M, int N, int K)
{
    constexpr int BM = 64, BN = 128, BK = 16;
    __shared__ __align__(16) float As[BK][BM + 4];   // As[k][m]
    __shared__ __align__(16) float Ws[BK][BN + 4];   // Ws[k][n]

    const float* __restrict__ A = devbuf(a_sel);
    float* __restrict__ C = (c_sel < 0) ? c_ext : devbuf(c_sel);

    const int tid  = threadIdx.x;
    const int tx   = tid & 15;    // cols tx*8 .. tx*8+7
    const int ty   = tid >> 4;    // rows ty*4 .. ty*4+3
    const int row0 = blockIdx.y * BM;
    const int col0 = blockIdx.x * BN;

    const int a_row = tid >> 2;
    const int a_col = (tid & 3) * 4;
    const int w_row = tid >> 5;
    const int w_col = (tid & 31) * 4;

    unsigned long long acc[4][4];
    #pragma unroll
    for (int i = 0; i < 4; i++)
        #pragma unroll
        for (int j = 0; j < 4; j++) acc[i][j] = 0ULL;

    const int  gr   = row0 + a_row;
    const bool a_ok = (gr < M);
    const int  gc   = col0 + w_col;
    const bool w_ok = (gc < N);

    for (int k0 = 0; k0 < K; k0 += BK) {
        float4 av = make_float4(0.f, 0.f, 0.f, 0.f);
        if (a_ok) av = *reinterpret_cast<const float4*>(A + (size_t)gr * K + k0 + a_col);
        As[a_col + 0][a_row] = av.x;
        As[a_col + 1][a_row] = av.y;
        As[a_col + 2][a_row] = av.z;
        As[a_col + 3][a_row] = av.w;
        #pragma unroll
        for (int r = 0; r < 2; r++) {
            const int wk = w_row + r * 8;
            float4 wv = make_float4(0.f, 0.f, 0.f, 0.f);
            if (w_ok) wv = *reinterpret_cast<const float4*>(W + (size_t)(k0 + wk) * N + gc);
            *reinterpret_cast<float4*>(&Ws[wk][w_col]) = wv;
        }
        __syncthreads();

        #pragma unroll
        for (int k = 0; k < BK; k++) {
            const float4 af = *reinterpret_cast<const float4*>(&As[k][ty * 4]);
            const float* wp = &Ws[k][tx * 8];
            unsigned long long w2[4];
            w2[0] = *reinterpret_cast<const unsigned long long*>(wp + 0);
            w2[1] = *reinterpret_cast<const unsigned long long*>(wp + 2);
            w2[2] = *reinterpret_cast<const unsigned long long*>(wp + 4);
            w2[3] = *reinterpret_cast<const unsigned long long*>(wp + 6);
            const float a4[4] = {af.x, af.y, af.z, af.w};
            #pragma unroll
            for (int i = 0; i < 4; i++) {
                const unsigned long long a2 = pack2(a4[i]);
                #pragma unroll
                for (int j = 0; j < 4; j++) fma2(acc[i][j], a2, w2[j]);
            }
        }
        __syncthreads();
    }

    #pragma unroll
    for (int i = 0; i < 4; i++) {
        const int r = row0 + ty * 4 + i;
        if (r >= M) continue;
        #pragma unroll
        for (int j = 0; j < 4; j++) {
            const int n0 = col0 + tx * 8 + 2 * j;
            const float2 c = unpack2(acc[i][j]);
            if (n0 < N) {
                float v = c.x + bias[n0];
                if (RELU) v = fmaxf(v, 0.f);
                C[(size_t)r * N + n0] = v;
            }
            if (n0 + 1 < N) {
                float v = c.y + bias[n0 + 1];
                if (RELU) v = fmaxf(v, 0.f);
                C[(size_t)r * N + n0 + 1] = v;
            }
        }
    }
}

// =============================== launch =====================================
extern "C" void kernel_launch(void* const* d_in, const int* in_sizes, int n_in,
                              void* d_out, int out_size)
{
    const float* x  = (const float*)d_in[0];
    const unsigned int* ei = (const unsigned int*)d_in[1];  // int32 OR int64 words
    const float* W1 = (const float*)d_in[2];
    const float* b1 = (const float*)d_in[3];
    const float* W2 = (const float*)d_in[4];
    const float* b2 = (const float*)d_in[5];
    const float* W3 = (const float*)d_in[6];
    const float* b3 = (const float*)d_in[7];
    const float* W4 = (const float*)d_in[8];
    const float* b4 = (const float*)d_in[9];
    const float* Wl = (const float*)d_in[10];
    const float* bl = (const float*)d_in[11];
    float* out = (float*)d_out;

    const int M = in_sizes[0] / 128;   // 50000 nodes
    const int E = in_sizes[1] / 2;     // 800000 edges
    const dim3 blk(256);
    const int nB   = (M + 255) / 256;
    const int eB   = (E + 255) / 256;
    const int aggB = (M * 32 + 255) / 256;     // one warp per node

    // ---- edge index normalize + CSR build (shared by both layers) ----
    detect_idx64 <<<1,  32 >>>(ei);
    convert_idx  <<<eB, blk>>>(ei, E, M);
    zero_deg     <<<nB, blk>>>(M);
    hist_deg     <<<eB, blk>>>(E);
    scan_block   <<<nB, blk>>>(M);
    scan_partials<<<1,  blk>>>(nB);
    scan_add     <<<nB, blk>>>(M, E);
    fill_csr     <<<eB, blk>>>(E);

    auto ggrid = [&](int n) { return dim3((n + 127) / 128, (M + 63) / 64); };

    // buffer ids: 0 = agg, 1 = bufA, 2 = bufB, -1 = external
    // ---- layer 1 ----
    gin_aggregate<<<aggB, blk>>>(x, 0, 0, M);
    sgemm_bias<true ><<<ggrid(128), blk>>>(0, W1, b1, 1, nullptr, M, 128, 128);
    sgemm_bias<true ><<<ggrid(128), blk>>>(1, W2, b2, 2, nullptr, M, 128, 128);

    // ---- layer 2 ----
    gin_aggregate<<<aggB, blk>>>(nullptr, 2, 0, M);
    sgemm_bias<true ><<<ggrid(256), blk>>>(0, W3, b3, 1, nullptr, M, 256, 128);
    sgemm_bias<true ><<<ggrid(256), blk>>>(1, W4, b4, 2, nullptr, M, 256, 256);

    // ---- head ----
    sgemm_bias<false><<<ggrid(40),  blk>>>(2, Wl, bl, -1, out, M, 40, 256);
}

// round 8
// speedup vs baseline: 1.3311x; 1.3046x over previous
#include <cuda_runtime.h>
#include <cstdint>

// ---------------------------------------------------------------------------
// GIN via mma.sync tf32 (3xTF32 emulated-fp32 GEMM) + CSR gather aggregation.
// N=50000 nodes, E=800000 edges, 128 -> (128,128) -> (256,256) -> 40.
// tcgen05 is unavailable (harness compiles PTX for base sm_103, not sm_103a),
// so GEMMs use legacy mma.sync.m16n8k8.tf32 register fragments.
// ---------------------------------------------------------------------------

#define MAXN 50000
#define MAXE 1000000

__device__ __align__(16) float g_agg [MAXN * 128];
__device__ __align__(16) float g_bufA[MAXN * 256];
__device__ __align__(16) float g_bufB[MAXN * 256];
__device__ int g_rowptr[MAXN + 1];
__device__ int g_cursor[MAXN];
__device__ int g_deg   [MAXN];
__device__ int g_srcs  [MAXE];
__device__ int g_src32 [MAXE];
__device__ int g_dst32 [MAXE];
__device__ int g_bsum  [256];
__device__ int g_is64;

__device__ __forceinline__ float* devbuf(int s) {
    if (s == 0) return g_agg;
    if (s == 1) return g_bufA;
    return g_bufB;
}

__device__ __forceinline__ float tf32_hi(float a) {
    uint32_t u;
    asm("cvt.rna.tf32.f32 %0, %1;" : "=r"(u) : "f"(a));
    return __uint_as_float(u);
}

#define MMA_TF32(d, a, b)                                                     \
    asm volatile(                                                             \
        "mma.sync.aligned.m16n8k8.row.col.f32.tf32.tf32.f32 "                 \
        "{%0,%1,%2,%3},{%4,%5,%6,%7},{%8,%9},{%0,%1,%2,%3};"                  \
        : "+f"((d)[0]), "+f"((d)[1]), "+f"((d)[2]), "+f"((d)[3])              \
        : "r"((a)[0]), "r"((a)[1]), "r"((a)[2]), "r"((a)[3]),                 \
          "r"((b)[0]), "r"((b)[1]))

// ======================= edge-index dtype handling ==========================
__global__ void detect_idx64(const unsigned int* __restrict__ w) {
    if (threadIdx.x == 0 && blockIdx.x == 0) {
        unsigned int o = 0;
        #pragma unroll 1
        for (int i = 1; i < 256; i += 2) o |= w[i];
        g_is64 = (o == 0) ? 1 : 0;
    }
}

__global__ void convert_idx(const unsigned int* __restrict__ w, int E, int N) {
    const int e = blockIdx.x * blockDim.x + threadIdx.x;
    if (e >= E) return;
    int s, d;
    if (g_is64) { s = (int)w[2 * e]; d = (int)w[2 * (E + e)]; }
    else        { s = (int)w[e];     d = (int)w[E + e]; }
    s = min(max(s, 0), N - 1);
    d = min(max(d, 0), N - 1);
    g_src32[e] = s;
    g_dst32[e] = d;
}

// ============================ CSR construction ==============================
__global__ void zero_deg(int N) {
    int i = blockIdx.x * blockDim.x + threadIdx.x;
    if (i < N) g_deg[i] = 0;
}
__global__ void hist_deg(int E) {
    int e = blockIdx.x * blockDim.x + threadIdx.x;
    if (e < E) atomicAdd(&g_deg[g_dst32[e]], 1);
}
__global__ void scan_block(int N) {
    __shared__ int s[256];
    const int t = threadIdx.x;
    const int i = blockIdx.x * 256 + t;
    const int v = (i < N) ? g_deg[i] : 0;
    s[t] = v;
    __syncthreads();
    #pragma unroll
    for (int off = 1; off < 256; off <<= 1) {
        int tmp = (t >= off) ? s[t - off] : 0;
        __syncthreads();
        s[t] += tmp;
        __syncthreads();
    }
    if (i < N) g_rowptr[i] = s[t] - v;
    if (t == 255) g_bsum[blockIdx.x] = s[255];
}
__global__ void scan_partials(int B) {
    __shared__ int s[256];
    const int t = threadIdx.x;
    const int v = (t < B) ? g_bsum[t] : 0;
    s[t] = v;
    __syncthreads();
    #pragma unroll
    for (int off = 1; off < 256; off <<= 1) {
        int tmp = (t >= off) ? s[t - off] : 0;
        __syncthreads();
        s[t] += tmp;
        __syncthreads();
    }
    if (t < B) g_bsum[t] = s[t] - v;
}
__global__ void scan_add(int N, int E) {
    int i = blockIdx.x * blockDim.x + threadIdx.x;
    if (i < N) {
        int r = g_rowptr[i] + g_bsum[blockIdx.x];
        g_rowptr[i] = r;
        g_cursor[i] = r;
    }
    if (i == N) g_rowptr[N] = E;
}
__global__ void fill_csr(int E) {
    int e = blockIdx.x * blockDim.x + threadIdx.x;
    if (e >= E) return;
    int p = atomicAdd(&g_cursor[g_dst32[e]], 1);
    g_srcs[p] = g_src32[e];
}

// ============================ GIN aggregation ===============================
__global__ void gin_aggregate(const float* __restrict__ h_ext,
                              int h_sel, int out_sel, int N) {
    const int warp = (blockIdx.x * blockDim.x + threadIdx.x) >> 5;
    if (warp >= N) return;
    const int lane = threadIdx.x & 31;
    const float* __restrict__ h = h_ext ? h_ext : devbuf(h_sel);
    float* __restrict__ out = devbuf(out_sel);
    const float4* __restrict__ hp = reinterpret_cast<const float4*>(h);
    float4 acc = hp[warp * 32 + lane];
    const int beg = g_rowptr[warp];
    const int end = g_rowptr[warp + 1];
    for (int j = beg; j < end; j++) {
        const int s = g_srcs[j];
        const float4 v = hp[s * 32 + lane];
        acc.x += v.x; acc.y += v.y; acc.z += v.z; acc.w += v.w;
    }
    reinterpret_cast<float4*>(out)[warp * 32 + lane] = acc;
}

// ======================= mma.sync tf32 3xTF32 GEMM ==========================
// C[M, N_real] = epi(A[M,K] @ W[K,N_real] + bias).
// Block tile 128x128 (N masked), 256 thr = 8 warps (2m x 4n), warp tile 64x32.
// BK=32 chunk staged in SMEM as hi/lo tf32 pairs; 3 mma passes -> ~fp32.
// SMEM (dynamic): Ahi[128][36], Alo[128][36], Whi[32][132], Wlo[32][132].
template<bool RELU>
__global__ void __launch_bounds__(256)
gemm_mma(int a_sel, int c_sel, float* __restrict__ c_ext,
         const float* __restrict__ W, const float* __restrict__ bias,
         int M, int N_real, int K)
{
    extern __shared__ __align__(16) float smem[];
    constexpr int AP = 36;    // A row pad
    constexpr int WP = 132;   // W row pad
    float* Ahi = smem;                       // 128*36
    float* Alo = Ahi + 128 * AP;             // 128*36
    float* Whi = Alo + 128 * AP;             // 32*132
    float* Wlo = Whi + 32 * WP;              // 32*132

    const int tid  = threadIdx.x;
    const int wid  = tid >> 5;
    const int lane = tid & 31;
    const int gid  = lane >> 2;    // 0..7
    const int tig  = lane & 3;     // 0..3
    const int wm   = wid >> 2;     // 0..1  -> m offset wm*64
    const int wn   = wid & 3;      // 0..3  -> n offset wn*32
    const int row0 = blockIdx.y * 128;
    const int col0 = blockIdx.x * 128;

    const float* __restrict__ A = devbuf(a_sel);
    float* __restrict__ C = (c_sel < 0) ? c_ext : devbuf(c_sel);

    // loaders: A row = tid>>1, 16 cols at (tid&1)*16 ; W k = tid>>3, 16 cols at (tid&7)*16
    const int a_r  = tid >> 1;
    const int a_c0 = (tid & 1) * 16;
    const int w_k  = tid >> 3;
    const int w_c0 = (tid & 7) * 16;
    const int a_gr = row0 + a_r;
    const bool a_ok = (a_gr < M);

    float acc[4][4][4];
    #pragma unroll
    for (int mt = 0; mt < 4; mt++)
        #pragma unroll
        for (int nt = 0; nt < 4; nt++)
            #pragma unroll
            for (int q = 0; q < 4; q++) acc[mt][nt][q] = 0.f;

    const int nchunks = K >> 5;
    for (int ch = 0; ch < nchunks; ch++) {
        const int k0 = ch << 5;
        // ---- stage A chunk (hi/lo) ----
        #pragma unroll
        for (int i = 0; i < 4; i++) {
            const int c = a_c0 + i * 4;
            float4 v = make_float4(0.f, 0.f, 0.f, 0.f);
            if (a_ok) v = *reinterpret_cast<const float4*>(A + (size_t)a_gr * K + k0 + c);
            float4 h, l;
            h.x = tf32_hi(v.x); l.x = tf32_hi(v.x - h.x);
            h.y = tf32_hi(v.y); l.y = tf32_hi(v.y - h.y);
            h.z = tf32_hi(v.z); l.z = tf32_hi(v.z - h.z);
            h.w = tf32_hi(v.w); l.w = tf32_hi(v.w - h.w);
            *reinterpret_cast<float4*>(&Ahi[a_r * AP + c]) = h;
            *reinterpret_cast<float4*>(&Alo[a_r * AP + c]) = l;
        }
        // ---- stage W chunk (hi/lo), zero-pad cols >= N_real ----
        #pragma unroll
        for (int i = 0; i < 4; i++) {
            const int c  = w_c0 + i * 4;
            const int gc = col0 + c;
            float4 v = make_float4(0.f, 0.f, 0.f, 0.f);
            if (gc < N_real)
                v = *reinterpret_cast<const float4*>(W + (size_t)(k0 + w_k) * N_real + gc);
            float4 h, l;
            h.x = tf32_hi(v.x); l.x = tf32_hi(v.x - h.x);
            h.y = tf32_hi(v.y); l.y = tf32_hi(v.y - h.y);
            h.z = tf32_hi(v.z); l.z = tf32_hi(v.z - h.z);
            h.w = tf32_hi(v.w); l.w = tf32_hi(v.w - h.w);
            *reinterpret_cast<float4*>(&Whi[w_k * WP + c]) = h;
            *reinterpret_cast<float4*>(&Wlo[w_k * WP + c]) = l;
        }
        __syncthreads();

        #pragma unroll
        for (int k8 = 0; k8 < 4; k8++) {
            const int kk = k8 * 8;
            uint32_t ah[4][4], al[4][4];
            #pragma unroll
            for (int mt = 0; mt < 4; mt++) {
                const int r = wm * 64 + mt * 16 + gid;
                const int cA = kk + tig;
                ah[mt][0] = __float_as_uint(Ahi[(r    ) * AP + cA    ]);
                ah[mt][1] = __float_as_uint(Ahi[(r + 8) * AP + cA    ]);
                ah[mt][2] = __float_as_uint(Ahi[(r    ) * AP + cA + 4]);
                ah[mt][3] = __float_as_uint(Ahi[(r + 8) * AP + cA + 4]);
                al[mt][0] = __float_as_uint(Alo[(r    ) * AP + cA    ]);
                al[mt][1] = __float_as_uint(Alo[(r + 8) * AP + cA    ]);
                al[mt][2] = __float_as_uint(Alo[(r    ) * AP + cA + 4]);
                al[mt][3] = __float_as_uint(Alo[(r + 8) * AP + cA + 4]);
            }
            uint32_t bh[4][2], bl[4][2];
            #pragma unroll
            for (int nt = 0; nt < 4; nt++) {
                const int c = wn * 32 + nt * 8 + gid;
                bh[nt][0] = __float_as_uint(Whi[(kk + tig    ) * WP + c]);
                bh[nt][1] = __float_as_uint(Whi[(kk + tig + 4) * WP + c]);
                bl[nt][0] = __float_as_uint(Wlo[(kk + tig    ) * WP + c]);
                bl[nt][1] = __float_as_uint(Wlo[(kk + tig + 4) * WP + c]);
            }
            #pragma unroll
            for (int mt = 0; mt < 4; mt++)
                #pragma unroll
                for (int nt = 0; nt < 4; nt++) {
                    MMA_TF32(acc[mt][nt], ah[mt], bh[nt]);   // hi*hi
                    MMA_TF32(acc[mt][nt], ah[mt], bl[nt]);   // hi*lo
                    MMA_TF32(acc[mt][nt], al[mt], bh[nt]);   // lo*hi
                }
        }
        __syncthreads();
    }

    // ---- epilogue: bias + relu, guarded stores ----
    #pragma unroll
    for (int mt = 0; mt < 4; mt++) {
        #pragma unroll
        for (int nt = 0; nt < 4; nt++) {
            const int c = col0 + wn * 32 + nt * 8 + 2 * tig;
            #pragma unroll
            for (int half = 0; half < 2; half++) {
                const int r = row0 + wm * 64 + mt * 16 + gid + half * 8;
                if (r >= M) continue;
                float v0 = acc[mt][nt][half * 2 + 0];
                float v1 = acc[mt][nt][half * 2 + 1];
                if (c < N_real) {
                    v0 += __ldg(&bias[c]);
                    if (RELU) v0 = fmaxf(v0, 0.f);
                }
                if (c + 1 < N_real) {
                    v1 += __ldg(&bias[c + 1]);
                    if (RELU) v1 = fmaxf(v1, 0.f);
                }
                if (c + 1 < N_real) {
                    float2 p = make_float2(v0, v1);
                    *reinterpret_cast<float2*>(C + (size_t)r * N_real + c) = p;
                } else if (c < N_real) {
                    C[(size_t)r * N_real + c] = v0;
                }
            }
        }
    }
}

// =============================== launch =====================================
extern "C" void kernel_launch(void* const* d_in, const int* in_sizes, int n_in,
                              void* d_out, int out_size)
{
    const float* x  = (const float*)d_in[0];
    const unsigned int* ei = (const unsigned int*)d_in[1];
    const float* W1 = (const float*)d_in[2];
    const float* b1 = (const float*)d_in[3];
    const float* W2 = (const float*)d_in[4];
    const float* b2 = (const float*)d_in[5];
    const float* W3 = (const float*)d_in[6];
    const float* b3 = (const float*)d_in[7];
    const float* W4 = (const float*)d_in[8];
    const float* b4 = (const float*)d_in[9];
    const float* Wl = (const float*)d_in[10];
    const float* bl = (const float*)d_in[11];
    float* out = (float*)d_out;

    const int M = in_sizes[0] / 128;   // 50000
    const int E = in_sizes[1] / 2;     // 800000
    const dim3 blk(256);
    const int nB   = (M + 255) / 256;
    const int eB   = (E + 255) / 256;
    const int aggB = (M * 32 + 255) / 256;
    const int mT   = (M + 127) / 128;  // 391 m-tiles

    const int SMB = (2 * 128 * 36 + 2 * 32 * 132) * 4;   // 70656 bytes
    cudaFuncSetAttribute(gemm_mma<true >, cudaFuncAttributeMaxDynamicSharedMemorySize, SMB);
    cudaFuncSetAttribute(gemm_mma<false>, cudaFuncAttributeMaxDynamicSharedMemorySize, SMB);

    // ---- edge index normalize + CSR build (shared by both layers) ----
    detect_idx64 <<<1,  32 >>>(ei);
    convert_idx  <<<eB, blk>>>(ei, E, M);
    zero_deg     <<<nB, blk>>>(M);
    hist_deg     <<<eB, blk>>>(E);
    scan_block   <<<nB, blk>>>(M);
    scan_partials<<<1,  blk>>>(nB);
    scan_add     <<<nB, blk>>>(M, E);
    fill_csr     <<<eB, blk>>>(E);

    // buffer ids: 0 = agg, 1 = bufA, 2 = bufB ; c_sel -1 = external out
    // ---- layer 1 ----
    gin_aggregate<<<aggB, blk>>>(x, 0, 0, M);
    gemm_mma<true ><<<dim3(1, mT), blk, SMB>>>(0, 1, nullptr, W1, b1, M, 128, 128);
    gemm_mma<true ><<<dim3(1, mT), blk, SMB>>>(1, 2, nullptr, W2, b2, M, 128, 128);

    // ---- layer 2 ----
    gin_aggregate<<<aggB, blk>>>(nullptr, 2, 0, M);
    gemm_mma<true ><<<dim3(2, mT), blk, SMB>>>(0, 1, nullptr, W3, b3, M, 256, 128);
    gemm_mma<true ><<<dim3(2, mT), blk, SMB>>>(1, 2, nullptr, W4, b4, M, 256, 256);

    // ---- head: N=40 (masked within one 128-wide tile) ----
    gemm_mma<false><<<dim3(1, mT), blk, SMB>>>(2, -1, out, Wl, bl, M, 40, 256);
}

// round 10
// speedup vs baseline: 1.9841x; 1.4906x over previous
#include <cuda_runtime.h>
#include <cuda_bf16.h>
#include <cstdint>

// ---------------------------------------------------------------------------
// GIN via mma.sync.m16n8k16.bf16 with double-bf16 split (3-product ~fp32):
//   a = a0 + a1 (bf16 each);  D += a0b0 + a0b1 + a1b0  (error ~2^-17/product)
// All GEMM operands pre-split & pair-packed (u32 = bf16[k],bf16[k+1]).
// NOTE: __device__ symbols are NEVER passed as kernel args from host code
// (host sees shadow symbol, not device address) — resolved on device instead.
// ---------------------------------------------------------------------------

#define MAXN 50000
#define MAXE 1000000

// split activation planes (u32 = packed bf16 pair along K), row len = K/2
__device__ __align__(16) unsigned g_P0[MAXN * 128];
__device__ __align__(16) unsigned g_P1[MAXN * 128];
__device__ __align__(16) unsigned g_Q0[MAXN * 128];
__device__ __align__(16) unsigned g_Q1[MAXN * 128];
__device__ __align__(16) float    g_hf[MAXN * 128];   // fp32 h1 (gather2 input)
__device__ __align__(16) unsigned g_W0[128 * 256];    // split weights [K/2][NW]
__device__ __align__(16) unsigned g_W1[128 * 256];
__device__ int g_rowptr[MAXN + 1];
__device__ int g_cursor[MAXN];
__device__ int g_deg   [MAXN];
__device__ int g_srcs  [MAXE];
__device__ int g_src32 [MAXE];
__device__ int g_dst32 [MAXE];
__device__ int g_bsum  [256];
__device__ int g_is64;

__device__ __forceinline__ const unsigned* planeR(int sel, int p) {
    if (sel == 0) return p ? g_P1 : g_P0;
    return p ? g_Q1 : g_Q0;
}
__device__ __forceinline__ unsigned* planeW(int sel, int p) {
    if (sel == 0) return p ? g_P1 : g_P0;
    return p ? g_Q1 : g_Q0;
}

// split two fp32 (even k, odd k) into primary/residual packed-bf16x2 words
__device__ __forceinline__ void split2(float e, float o,
                                       unsigned& hi, unsigned& lo) {
    __nv_bfloat16 he = __float2bfloat16_rn(e);
    __nv_bfloat16 ho = __float2bfloat16_rn(o);
    float re = e - __bfloat162float(he);
    float ro = o - __bfloat162float(ho);
    __nv_bfloat16 rhe = __float2bfloat16_rn(re);
    __nv_bfloat16 rho = __float2bfloat16_rn(ro);
    hi = ((unsigned)__bfloat16_as_ushort(ho) << 16) | __bfloat16_as_ushort(he);
    lo = ((unsigned)__bfloat16_as_ushort(rho) << 16) | __bfloat16_as_ushort(rhe);
}

#define MMA_BF16(d, a, b)                                                     \
    asm volatile(                                                             \
        "mma.sync.aligned.m16n8k16.row.col.f32.bf16.bf16.f32 "               \
        "{%0,%1,%2,%3},{%4,%5,%6,%7},{%8,%9},{%0,%1,%2,%3};"                 \
        : "+f"((d)[0]), "+f"((d)[1]), "+f"((d)[2]), "+f"((d)[3])             \
        : "r"((a)[0]), "r"((a)[1]), "r"((a)[2]), "r"((a)[3]),                \
          "r"((b)[0]), "r"((b)[1]))

// ======================= edge-index dtype handling ==========================
__global__ void detect_idx64(const unsigned int* __restrict__ w) {
    if (threadIdx.x == 0 && blockIdx.x == 0) {
        unsigned int o = 0;
        #pragma unroll 1
        for (int i = 1; i < 256; i += 2) o |= w[i];
        g_is64 = (o == 0) ? 1 : 0;
    }
}
__global__ void convert_idx(const unsigned int* __restrict__ w, int E, int N) {
    const int e = blockIdx.x * blockDim.x + threadIdx.x;
    if (e >= E) return;
    int s, d;
    if (g_is64) { s = (int)w[2 * e]; d = (int)w[2 * (E + e)]; }
    else        { s = (int)w[e];     d = (int)w[E + e]; }
    s = min(max(s, 0), N - 1);
    d = min(max(d, 0), N - 1);
    g_src32[e] = s;
    g_dst32[e] = d;
}

// ============================ CSR construction ==============================
__global__ void zero_deg(int N) {
    int i = blockIdx.x * blockDim.x + threadIdx.x;
    if (i < N) g_deg[i] = 0;
}
__global__ void hist_deg(int E) {
    int e = blockIdx.x * blockDim.x + threadIdx.x;
    if (e < E) atomicAdd(&g_deg[g_dst32[e]], 1);
}
__global__ void scan_block(int N) {
    __shared__ int s[256];
    const int t = threadIdx.x;
    const int i = blockIdx.x * 256 + t;
    const int v = (i < N) ? g_deg[i] : 0;
    s[t] = v;
    __syncthreads();
    #pragma unroll
    for (int off = 1; off < 256; off <<= 1) {
        int tmp = (t >= off) ? s[t - off] : 0;
        __syncthreads();
        s[t] += tmp;
        __syncthreads();
    }
    if (i < N) g_rowptr[i] = s[t] - v;
    if (t == 255) g_bsum[blockIdx.x] = s[255];
}
__global__ void scan_partials(int B) {
    __shared__ int s[256];
    const int t = threadIdx.x;
    const int v = (t < B) ? g_bsum[t] : 0;
    s[t] = v;
    __syncthreads();
    #pragma unroll
    for (int off = 1; off < 256; off <<= 1) {
        int tmp = (t >= off) ? s[t - off] : 0;
        __syncthreads();
        s[t] += tmp;
        __syncthreads();
    }
    if (t < B) g_bsum[t] = s[t] - v;
}
__global__ void scan_add(int N, int E) {
    int i = blockIdx.x * blockDim.x + threadIdx.x;
    if (i < N) {
        int r = g_rowptr[i] + g_bsum[blockIdx.x];
        g_rowptr[i] = r;
        g_cursor[i] = r;
    }
    if (i == N) g_rowptr[N] = E;
}
__global__ void fill_csr(int E) {
    int e = blockIdx.x * blockDim.x + threadIdx.x;
    if (e >= E) return;
    int p = atomicAdd(&g_cursor[g_dst32[e]], 1);
    g_srcs[p] = g_src32[e];
}

// ===================== GIN aggregation (split output) =======================
// h = use_ext ? h_ext : g_hf (device-resolved!). Output -> P planes.
__global__ void gin_aggregate_split(const float* __restrict__ h_ext,
                                    int use_ext, int N) {
    const int warp = (blockIdx.x * blockDim.x + threadIdx.x) >> 5;
    if (warp >= N) return;
    const int lane = threadIdx.x & 31;
    const float* __restrict__ h = use_ext ? h_ext : g_hf;
    const float4* __restrict__ hp = reinterpret_cast<const float4*>(h);
    float4 acc = hp[(size_t)warp * 32 + lane];
    const int beg = g_rowptr[warp];
    const int end = g_rowptr[warp + 1];
    for (int j = beg; j < end; j++) {
        const int s = g_srcs[j];
        const float4 v = hp[(size_t)s * 32 + lane];
        acc.x += v.x; acc.y += v.y; acc.z += v.z; acc.w += v.w;
    }
    unsigned h0, l0, h1, l1;
    split2(acc.x, acc.y, h0, l0);
    split2(acc.z, acc.w, h1, l1);
    const size_t o = (size_t)warp * 32 + lane;   // uint2 idx, row = 32 uint2
    reinterpret_cast<uint2*>(g_P0)[o] = make_uint2(h0, h1);
    reinterpret_cast<uint2*>(g_P1)[o] = make_uint2(l0, l1);
}

// ===================== weight split/pack: W[K][N] -> [K/2][NW] ==============
__global__ void prep_w(const float* __restrict__ W, int K, int N_real, int NW) {
    int idx = blockIdx.x * blockDim.x + threadIdx.x;
    if (idx >= (K >> 1) * NW) return;
    int kp = idx / NW, n = idx % NW;
    float e = 0.f, o = 0.f;
    if (n < N_real) {
        e = W[(size_t)(2 * kp) * N_real + n];
        o = W[(size_t)(2 * kp + 1) * N_real + n];
    }
    unsigned hi, lo;
    split2(e, o, hi, lo);
    g_W0[idx] = hi;
    g_W1[idx] = lo;
}

// ======================= bf16x3 GEMM (mma.m16n8k16) =========================
// C[M,N_real] = epi(A @ W + bias). Block 128x128, 8 warps (2m x 4n),
// warp 64x32, BK=32 (2 k16 steps). Register-prefetch pipelined staging.
// CMODE: 0 = split planes (c_sel), 1 = fp32 g_hf, 2 = external fp32 (masked).
template<bool RELU, int CMODE>
__global__ void __launch_bounds__(256, 1)
gemm_bf16(int a_sel, int c_sel, float* __restrict__ c_ext,
          const float* __restrict__ bias, int M, int N_real, int NW, int K)
{
    extern __shared__ __align__(16) unsigned smem[];
    unsigned* As0 = smem;                  // [128][20]
    unsigned* As1 = As0 + 128 * 20;
    unsigned* Bs0 = As1 + 128 * 20;        // [16][136]
    unsigned* Bs1 = Bs0 + 16 * 136;

    const int tid  = threadIdx.x;
    const int wid  = tid >> 5;
    const int lane = tid & 31;
    const int gid  = lane >> 2;
    const int tig  = lane & 3;
    const int wm   = wid >> 2;
    const int wn   = wid & 3;
    const int row0 = blockIdx.y * 128;
    const int col0 = blockIdx.x * 128;

    const unsigned* __restrict__ A0g = planeR(a_sel, 0);
    const unsigned* __restrict__ A1g = planeR(a_sel, 1);

    const int a_r = tid >> 1, a_seg = (tid & 1) * 8;
    const int b_kp = tid >> 4, b_c0 = (tid & 15) * 8;
    const int a_gr = row0 + a_r;
    const bool a_ok = (a_gr < M);
    const int Kh = K >> 1;

    float acc[4][4][4];
    #pragma unroll
    for (int mt = 0; mt < 4; mt++)
        #pragma unroll
        for (int nt = 0; nt < 4; nt++)
            #pragma unroll
            for (int q = 0; q < 4; q++) acc[mt][nt][q] = 0.f;

    uint4 pa0[2], pa1[2], pb0[2], pb1[2];
    auto load_chunk = [&](int ch) {
        const int kp0 = ch << 4;
        if (a_ok) {
            const unsigned* p = A0g + (size_t)a_gr * Kh + kp0 + a_seg;
            pa0[0] = *reinterpret_cast<const uint4*>(p);
            pa0[1] = *reinterpret_cast<const uint4*>(p + 4);
            p = A1g + (size_t)a_gr * Kh + kp0 + a_seg;
            pa1[0] = *reinterpret_cast<const uint4*>(p);
            pa1[1] = *reinterpret_cast<const uint4*>(p + 4);
        } else {
            pa0[0] = pa0[1] = pa1[0] = pa1[1] = make_uint4(0, 0, 0, 0);
        }
        const unsigned* q = g_W0 + (size_t)(kp0 + b_kp) * NW + col0 + b_c0;
        pb0[0] = *reinterpret_cast<const uint4*>(q);
        pb0[1] = *reinterpret_cast<const uint4*>(q + 4);
        q = g_W1 + (size_t)(kp0 + b_kp) * NW + col0 + b_c0;
        pb1[0] = *reinterpret_cast<const uint4*>(q);
        pb1[1] = *reinterpret_cast<const uint4*>(q + 4);
    };

    load_chunk(0);
    const int nch = K >> 5;
    for (int ch = 0; ch < nch; ch++) {
        *reinterpret_cast<uint4*>(&As0[a_r * 20 + a_seg])     = pa0[0];
        *reinterpret_cast<uint4*>(&As0[a_r * 20 + a_seg + 4]) = pa0[1];
        *reinterpret_cast<uint4*>(&As1[a_r * 20 + a_seg])     = pa1[0];
        *reinterpret_cast<uint4*>(&As1[a_r * 20 + a_seg + 4]) = pa1[1];
        *reinterpret_cast<uint4*>(&Bs0[b_kp * 136 + b_c0])     = pb0[0];
        *reinterpret_cast<uint4*>(&Bs0[b_kp * 136 + b_c0 + 4]) = pb0[1];
        *reinterpret_cast<uint4*>(&Bs1[b_kp * 136 + b_c0])     = pb1[0];
        *reinterpret_cast<uint4*>(&Bs1[b_kp * 136 + b_c0 + 4]) = pb1[1];
        __syncthreads();
        if (ch + 1 < nch) load_chunk(ch + 1);   // overlap LDG with MMA

        #pragma unroll
        for (int s = 0; s < 2; s++) {
            const int so = s * 8;
            uint32_t A0f[4][4], A1f[4][4];
            #pragma unroll
            for (int mt = 0; mt < 4; mt++) {
                const int r = wm * 64 + mt * 16 + gid;
                A0f[mt][0] = As0[(r    ) * 20 + so + tig    ];
                A0f[mt][1] = As0[(r + 8) * 20 + so + tig    ];
                A0f[mt][2] = As0[(r    ) * 20 + so + tig + 4];
                A0f[mt][3] = As0[(r + 8) * 20 + so + tig + 4];
                A1f[mt][0] = As1[(r    ) * 20 + so + tig    ];
                A1f[mt][1] = As1[(r + 8) * 20 + so + tig    ];
                A1f[mt][2] = As1[(r    ) * 20 + so + tig + 4];
                A1f[mt][3] = As1[(r + 8) * 20 + so + tig + 4];
            }
            uint32_t B0f[4][2], B1f[4][2];
            #pragma unroll
            for (int nt = 0; nt < 4; nt++) {
                const int c = wn * 32 + nt * 8 + gid;
                B0f[nt][0] = Bs0[(so + tig    ) * 136 + c];
                B0f[nt][1] = Bs0[(so + tig + 4) * 136 + c];
                B1f[nt][0] = Bs1[(so + tig    ) * 136 + c];
                B1f[nt][1] = Bs1[(so + tig + 4) * 136 + c];
            }
            #pragma unroll
            for (int mt = 0; mt < 4; mt++)
                #pragma unroll
                for (int nt = 0; nt < 4; nt++)
                    MMA_BF16(acc[mt][nt], A0f[mt], B0f[nt]);   // a0*b0
            #pragma unroll
            for (int mt = 0; mt < 4; mt++)
                #pragma unroll
                for (int nt = 0; nt < 4; nt++)
                    MMA_BF16(acc[mt][nt], A0f[mt], B1f[nt]);   // a0*b1
            #pragma unroll
            for (int mt = 0; mt < 4; mt++)
                #pragma unroll
                for (int nt = 0; nt < 4; nt++)
                    MMA_BF16(acc[mt][nt], A1f[mt], B0f[nt]);   // a1*b0
        }
        __syncthreads();
    }

    // ---- epilogue ----
    unsigned* C0 = planeW(c_sel, 0);
    unsigned* C1 = planeW(c_sel, 1);
    #pragma unroll
    for (int mt = 0; mt < 4; mt++) {
        #pragma unroll
        for (int nt = 0; nt < 4; nt++) {
            const int c = col0 + wn * 32 + nt * 8 + 2 * tig;
            #pragma unroll
            for (int half = 0; half < 2; half++) {
                const int r = row0 + wm * 64 + mt * 16 + gid + half * 8;
                if (r >= M) continue;
                float v0 = acc[mt][nt][half * 2 + 0];
                float v1 = acc[mt][nt][half * 2 + 1];
                if (CMODE == 2) {
                    if (c < N_real) {
                        v0 += __ldg(&bias[c]);
                        if (RELU) v0 = fmaxf(v0, 0.f);
                        c_ext[(size_t)r * N_real + c] = v0;
                    }
                    if (c + 1 < N_real) {
                        v1 += __ldg(&bias[c + 1]);
                        if (RELU) v1 = fmaxf(v1, 0.f);
                        c_ext[(size_t)r * N_real + c + 1] = v1;
                    }
                } else {
                    v0 += __ldg(&bias[c]);
                    v1 += __ldg(&bias[c + 1]);
                    if (RELU) { v0 = fmaxf(v0, 0.f); v1 = fmaxf(v1, 0.f); }
                    if (CMODE == 1) {
                        *reinterpret_cast<float2*>(&g_hf[(size_t)r * N_real + c]) =
                            make_float2(v0, v1);
                    } else {
                        unsigned hi, lo;
                        split2(v0, v1, hi, lo);
                        const size_t o = (size_t)r * (N_real >> 1) + (c >> 1);
                        C0[o] = hi;
                        C1[o] = lo;
                    }
                }
            }
        }
    }
}

// =============================== launch =====================================
extern "C" void kernel_launch(void* const* d_in, const int* in_sizes, int n_in,
                              void* d_out, int out_size)
{
    const float* x  = (const float*)d_in[0];
    const unsigned int* ei = (const unsigned int*)d_in[1];
    const float* W1 = (const float*)d_in[2];
    const float* b1 = (const float*)d_in[3];
    const float* W2 = (const float*)d_in[4];
    const float* b2 = (const float*)d_in[5];
    const float* W3 = (const float*)d_in[6];
    const float* b3 = (const float*)d_in[7];
    const float* W4 = (const float*)d_in[8];
    const float* b4 = (const float*)d_in[9];
    const float* Wl = (const float*)d_in[10];
    const float* bl = (const float*)d_in[11];
    float* out = (float*)d_out;

    const int M = in_sizes[0] / 128;   // 50000
    const int E = in_sizes[1] / 2;     // 800000
    const dim3 blk(256);
    const int nB   = (M + 255) / 256;
    const int eB   = (E + 255) / 256;
    const int aggB = (M * 32 + 255) / 256;
    const int mT   = (M + 127) / 128;

    const int SMB = (2 * 128 * 20 + 2 * 16 * 136) * 4;   // 37888 B
    cudaFuncSetAttribute(gemm_bf16<true , 0>, cudaFuncAttributeMaxDynamicSharedMemorySize, SMB);
    cudaFuncSetAttribute(gemm_bf16<true , 1>, cudaFuncAttributeMaxDynamicSharedMemorySize, SMB);
    cudaFuncSetAttribute(gemm_bf16<false, 2>, cudaFuncAttributeMaxDynamicSharedMemorySize, SMB);

    auto pgrid = [&](int k, int nw) { return ((k >> 1) * nw + 255) / 256; };

    // ---- edge index normalize + CSR build (shared by both layers) ----
    detect_idx64 <<<1,  32 >>>(ei);
    convert_idx  <<<eB, blk>>>(ei, E, M);
    zero_deg     <<<nB, blk>>>(M);
    hist_deg     <<<eB, blk>>>(E);
    scan_block   <<<nB, blk>>>(M);
    scan_partials<<<1,  blk>>>(nB);
    scan_add     <<<nB, blk>>>(M, E);
    fill_csr     <<<eB, blk>>>(E);

    // ---- layer 1 (128 -> 128 -> 128) ----
    gin_aggregate_split<<<aggB, blk>>>(x, 1, M);                         // x -> P
    prep_w<<<pgrid(128, 128), blk>>>(W1, 128, 128, 128);
    gemm_bf16<true , 0><<<dim3(1, mT), blk, SMB>>>(0, 1, nullptr, b1, M, 128, 128, 128); // P -> Q
    prep_w<<<pgrid(128, 128), blk>>>(W2, 128, 128, 128);
    gemm_bf16<true , 1><<<dim3(1, mT), blk, SMB>>>(1, 0, nullptr, b2, M, 128, 128, 128); // Q -> g_hf

    // ---- layer 2 (128 -> 256 -> 256) ----
    gin_aggregate_split<<<aggB, blk>>>(nullptr, 0, M);                   // g_hf -> P (device-resolved)
    prep_w<<<pgrid(128, 256), blk>>>(W3, 128, 256, 256);
    gemm_bf16<true , 0><<<dim3(2, mT), blk, SMB>>>(0, 1, nullptr, b3, M, 256, 256, 128); // P -> Q
    prep_w<<<pgrid(256, 256), blk>>>(W4, 256, 256, 256);
    gemm_bf16<true , 0><<<dim3(2, mT), blk, SMB>>>(1, 0, nullptr, b4, M, 256, 256, 256); // Q -> P

    // ---- head (256 -> 40, masked in one 128-wide tile) ----
    prep_w<<<pgrid(256, 128), blk>>>(Wl, 256, 40, 128);
    gemm_bf16<false, 2><<<dim3(1, mT), blk, SMB>>>(0, 0, out, bl, M, 40, 128, 256);      // P -> out
}

// round 11
// speedup vs baseline: 2.3859x; 1.2025x over previous
#include <cuda_runtime.h>
#include <cuda_bf16.h>
#include <cstdint>

// ---------------------------------------------------------------------------
// GIN via mma.sync.m16n8k16.bf16 double-bf16 split (3-product ~fp32):
//   a = a0 + a1 (bf16 each);  D += a0b0 + a0b1 + a1b0  (err ~2^-17/product)
// GEMM: cp.async.cg double-buffered staging, 2 CTAs/SM, 8 warps (2m x 4n),
// warp tile 64x32, BK=32. Operands pre-split & pair-packed (u32 = bf16 pair).
// ---------------------------------------------------------------------------

#define MAXN 50000
#define MAXE 1000000

__device__ __align__(16) unsigned g_P0[MAXN * 128];
__device__ __align__(16) unsigned g_P1[MAXN * 128];
__device__ __align__(16) unsigned g_Q0[MAXN * 128];
__device__ __align__(16) unsigned g_Q1[MAXN * 128];
__device__ __align__(16) float    g_hf[MAXN * 128];   // fp32 h1 (gather2 input)
__device__ __align__(16) unsigned g_W0[128 * 256];    // split weights [K/2][NW]
__device__ __align__(16) unsigned g_W1[128 * 256];
__device__ int g_rowptr[MAXN + 1];
__device__ int g_cursor[MAXN];
__device__ int g_deg   [MAXN];
__device__ int g_srcs  [MAXE];
__device__ int g_src32 [MAXE];
__device__ int g_dst32 [MAXE];
__device__ int g_bsum  [256];
__device__ int g_is64;

__device__ __forceinline__ const unsigned* planeR(int sel, int p) {
    if (sel == 0) return p ? g_P1 : g_P0;
    return p ? g_Q1 : g_Q0;
}
__device__ __forceinline__ unsigned* planeW(int sel, int p) {
    if (sel == 0) return p ? g_P1 : g_P0;
    return p ? g_Q1 : g_Q0;
}

__device__ __forceinline__ void split2(float e, float o,
                                       unsigned& hi, unsigned& lo) {
    __nv_bfloat16 he = __float2bfloat16_rn(e);
    __nv_bfloat16 ho = __float2bfloat16_rn(o);
    float re = e - __bfloat162float(he);
    float ro = o - __bfloat162float(ho);
    __nv_bfloat16 rhe = __float2bfloat16_rn(re);
    __nv_bfloat16 rho = __float2bfloat16_rn(ro);
    hi = ((unsigned)__bfloat16_as_ushort(ho) << 16) | __bfloat16_as_ushort(he);
    lo = ((unsigned)__bfloat16_as_ushort(rho) << 16) | __bfloat16_as_ushort(rhe);
}

#define MMA_BF16(d, a, b)                                                     \
    asm volatile(                                                             \
        "mma.sync.aligned.m16n8k16.row.col.f32.bf16.bf16.f32 "               \
        "{%0,%1,%2,%3},{%4,%5,%6,%7},{%8,%9},{%0,%1,%2,%3};"                 \
        : "+f"((d)[0]), "+f"((d)[1]), "+f"((d)[2]), "+f"((d)[3])             \
        : "r"((a)[0]), "r"((a)[1]), "r"((a)[2]), "r"((a)[3]),                \
          "r"((b)[0]), "r"((b)[1]))

// 16B cp.async with zero-fill when pred is false (src-size=0 form)
__device__ __forceinline__ void cp16(uint32_t dst, const void* src, bool pred) {
    int sz = pred ? 16 : 0;
    asm volatile("cp.async.cg.shared.global [%0], [%1], 16, %2;"
                 :: "r"(dst), "l"(src), "r"(sz) : "memory");
}
#define CP_COMMIT() asm volatile("cp.async.commit_group;" ::: "memory")
#define CP_WAIT(n)  asm volatile("cp.async.wait_group %0;" :: "n"(n) : "memory")

// ======================= edge-index dtype handling ==========================
__global__ void detect_idx64(const unsigned int* __restrict__ w) {
    if (threadIdx.x == 0 && blockIdx.x == 0) {
        unsigned int o = 0;
        #pragma unroll 1
        for (int i = 1; i < 256; i += 2) o |= w[i];
        g_is64 = (o == 0) ? 1 : 0;
    }
}
__global__ void convert_idx(const unsigned int* __restrict__ w, int E, int N) {
    const int e = blockIdx.x * blockDim.x + threadIdx.x;
    if (e >= E) return;
    int s, d;
    if (g_is64) { s = (int)w[2 * e]; d = (int)w[2 * (E + e)]; }
    else        { s = (int)w[e];     d = (int)w[E + e]; }
    s = min(max(s, 0), N - 1);
    d = min(max(d, 0), N - 1);
    g_src32[e] = s;
    g_dst32[e] = d;
}

// ============================ CSR construction ==============================
__global__ void zero_deg(int N) {
    int i = blockIdx.x * blockDim.x + threadIdx.x;
    if (i < N) g_deg[i] = 0;
}
__global__ void hist_deg(int E) {
    int e = blockIdx.x * blockDim.x + threadIdx.x;
    if (e < E) atomicAdd(&g_deg[g_dst32[e]], 1);
}
__global__ void scan_block(int N) {
    __shared__ int s[256];
    const int t = threadIdx.x;
    const int i = blockIdx.x * 256 + t;
    const int v = (i < N) ? g_deg[i] : 0;
    s[t] = v;
    __syncthreads();
    #pragma unroll
    for (int off = 1; off < 256; off <<= 1) {
        int tmp = (t >= off) ? s[t - off] : 0;
        __syncthreads();
        s[t] += tmp;
        __syncthreads();
    }
    if (i < N) g_rowptr[i] = s[t] - v;
    if (t == 255) g_bsum[blockIdx.x] = s[255];
}
__global__ void scan_partials(int B) {
    __shared__ int s[256];
    const int t = threadIdx.x;
    const int v = (t < B) ? g_bsum[t] : 0;
    s[t] = v;
    __syncthreads();
    #pragma unroll
    for (int off = 1; off < 256; off <<= 1) {
        int tmp = (t >= off) ? s[t - off] : 0;
        __syncthreads();
        s[t] += tmp;
        __syncthreads();
    }
    if (t < B) g_bsum[t] = s[t] - v;
}
__global__ void scan_add(int N, int E) {
    int i = blockIdx.x * blockDim.x + threadIdx.x;
    if (i < N) {
        int r = g_rowptr[i] + g_bsum[blockIdx.x];
        g_rowptr[i] = r;
        g_cursor[i] = r;
    }
    if (i == N) g_rowptr[N] = E;
}
__global__ void fill_csr(int E) {
    int e = blockIdx.x * blockDim.x + threadIdx.x;
    if (e >= E) return;
    int p = atomicAdd(&g_cursor[g_dst32[e]], 1);
    g_srcs[p] = g_src32[e];
}

// ===================== GIN aggregation (split output) =======================
__global__ void gin_aggregate_split(const float* __restrict__ h_ext,
                                    int use_ext, int N) {
    const int warp = (blockIdx.x * blockDim.x + threadIdx.x) >> 5;
    if (warp >= N) return;
    const int lane = threadIdx.x & 31;
    const float* __restrict__ h = use_ext ? h_ext : g_hf;
    const float4* __restrict__ hp = reinterpret_cast<const float4*>(h);
    float4 acc = hp[(size_t)warp * 32 + lane];
    const int beg = g_rowptr[warp];
    const int end = g_rowptr[warp + 1];
    for (int j = beg; j < end; j++) {
        const int s = g_srcs[j];
        const float4 v = hp[(size_t)s * 32 + lane];
        acc.x += v.x; acc.y += v.y; acc.z += v.z; acc.w += v.w;
    }
    unsigned h0, l0, h1, l1;
    split2(acc.x, acc.y, h0, l0);
    split2(acc.z, acc.w, h1, l1);
    const size_t o = (size_t)warp * 32 + lane;
    reinterpret_cast<uint2*>(g_P0)[o] = make_uint2(h0, h1);
    reinterpret_cast<uint2*>(g_P1)[o] = make_uint2(l0, l1);
}

// ===================== weight split/pack: W[K][N] -> [K/2][NW] ==============
__global__ void prep_w(const float* __restrict__ W, int K, int N_real, int NW) {
    int idx = blockIdx.x * blockDim.x + threadIdx.x;
    if (idx >= (K >> 1) * NW) return;
    int kp = idx / NW, n = idx % NW;
    float e = 0.f, o = 0.f;
    if (n < N_real) {
        e = W[(size_t)(2 * kp) * N_real + n];
        o = W[(size_t)(2 * kp + 1) * N_real + n];
    }
    unsigned hi, lo;
    split2(e, o, hi, lo);
    g_W0[idx] = hi;
    g_W1[idx] = lo;
}

// ======================= bf16x3 GEMM (mma.m16n8k16) =========================
// cp.async double-buffered. Per stage (u32): As0[128][20] As1 Bs0[16][136] Bs1
// Stage stride = 2*2560 + 2*2176 = 9472 u32. Two stages = 75776 B.
// CMODE: 0 = split planes (c_sel), 1 = fp32 g_hf, 2 = external fp32 (masked).
template<bool RELU, int CMODE>
__global__ void __launch_bounds__(256, 2)
gemm_bf16(int a_sel, int c_sel, float* __restrict__ c_ext,
          const float* __restrict__ bias, int M, int N_real, int NW, int K)
{
    extern __shared__ __align__(16) unsigned smem[];
    constexpr int STG = 9472;            // u32 per stage
    const uint32_t smem_b = (uint32_t)__cvta_generic_to_shared(smem);

    const int tid  = threadIdx.x;
    const int wid  = tid >> 5;
    const int lane = tid & 31;
    const int gid  = lane >> 2;
    const int tig  = lane & 3;
    const int wm   = wid >> 2;
    const int wn   = wid & 3;
    const int row0 = blockIdx.y * 128;
    const int col0 = blockIdx.x * 128;

    const unsigned* __restrict__ A0g = planeR(a_sel, 0);
    const unsigned* __restrict__ A1g = planeR(a_sel, 1);

    const int a_r = tid >> 1, a_seg = (tid & 1) * 8;
    const int b_kp = tid >> 4, b_c0 = (tid & 15) * 8;
    const int a_gr = row0 + a_r;
    const bool a_ok = (a_gr < M);
    const int Kh = K >> 1;

    float acc[4][4][4];
    #pragma unroll
    for (int mt = 0; mt < 4; mt++)
        #pragma unroll
        for (int nt = 0; nt < 4; nt++)
            #pragma unroll
            for (int q = 0; q < 4; q++) acc[mt][nt][q] = 0.f;

    // stage chunk ch into buffer buf (8 x 16B cp.async per thread)
    auto stage = [&](int ch, int buf) {
        const int kp0 = ch << 4;
        const uint32_t sb = smem_b + (uint32_t)(buf * STG) * 4u;
        const uint32_t a_off = (uint32_t)(a_r * 20 + a_seg) * 4u;
        cp16(sb + a_off,      A0g + (size_t)a_gr * Kh + kp0 + a_seg,     a_ok);
        cp16(sb + a_off + 16, A0g + (size_t)a_gr * Kh + kp0 + a_seg + 4, a_ok);
        cp16(sb + 2560u * 4u + a_off,      A1g + (size_t)a_gr * Kh + kp0 + a_seg,     a_ok);
        cp16(sb + 2560u * 4u + a_off + 16, A1g + (size_t)a_gr * Kh + kp0 + a_seg + 4, a_ok);
        const uint32_t b_off = (uint32_t)(b_kp * 136 + b_c0) * 4u;
        const size_t bg = (size_t)(kp0 + b_kp) * NW + col0 + b_c0;
        cp16(sb + 5120u * 4u + b_off,      g_W0 + bg,     true);
        cp16(sb + 5120u * 4u + b_off + 16, g_W0 + bg + 4, true);
        cp16(sb + 7296u * 4u + b_off,      g_W1 + bg,     true);
        cp16(sb + 7296u * 4u + b_off + 16, g_W1 + bg + 4, true);
        CP_COMMIT();
    };

    const int nch = K >> 5;
    stage(0, 0);
    for (int ch = 0; ch < nch; ch++) {
        if (ch + 1 < nch) {
            stage(ch + 1, (ch + 1) & 1);
            CP_WAIT(1);
        } else {
            CP_WAIT(0);
        }
        __syncthreads();

        const unsigned* S   = smem + (ch & 1) * STG;
        const unsigned* As0 = S;
        const unsigned* As1 = S + 2560;
        const unsigned* Bs0 = S + 5120;
        const unsigned* Bs1 = S + 7296;

        #pragma unroll
        for (int s = 0; s < 2; s++) {
            const int so = s * 8;
            uint32_t B0f[4][2], B1f[4][2];
            #pragma unroll
            for (int nt = 0; nt < 4; nt++) {
                const int c = wn * 32 + nt * 8 + gid;
                B0f[nt][0] = Bs0[(so + tig    ) * 136 + c];
                B0f[nt][1] = Bs0[(so + tig + 4) * 136 + c];
                B1f[nt][0] = Bs1[(so + tig    ) * 136 + c];
                B1f[nt][1] = Bs1[(so + tig + 4) * 136 + c];
            }
            #pragma unroll
            for (int mt = 0; mt < 4; mt++) {
                const int r = wm * 64 + mt * 16 + gid;
                uint32_t A0f[4], A1f[4];
                A0f[0] = As0[(r    ) * 20 + so + tig    ];
                A0f[1] = As0[(r + 8) * 20 + so + tig    ];
                A0f[2] = As0[(r    ) * 20 + so + tig + 4];
                A0f[3] = As0[(r + 8) * 20 + so + tig + 4];
                A1f[0] = As1[(r    ) * 20 + so + tig    ];
                A1f[1] = As1[(r + 8) * 20 + so + tig    ];
                A1f[2] = As1[(r    ) * 20 + so + tig + 4];
                A1f[3] = As1[(r + 8) * 20 + so + tig + 4];
                #pragma unroll
                for (int nt = 0; nt < 4; nt++)
                    MMA_BF16(acc[mt][nt], A0f, B0f[nt]);   // a0*b0
                #pragma unroll
                for (int nt = 0; nt < 4; nt++)
                    MMA_BF16(acc[mt][nt], A0f, B1f[nt]);   // a0*b1
                #pragma unroll
                for (int nt = 0; nt < 4; nt++)
                    MMA_BF16(acc[mt][nt], A1f, B0f[nt]);   // a1*b0
            }
        }
        __syncthreads();
    }

    // ---- epilogue ----
    unsigned* C0 = planeW(c_sel, 0);
    unsigned* C1 = planeW(c_sel, 1);
    #pragma unroll
    for (int mt = 0; mt < 4; mt++) {
        #pragma unroll
        for (int nt = 0; nt < 4; nt++) {
            const int c = col0 + wn * 32 + nt * 8 + 2 * tig;
            #pragma unroll
            for (int half = 0; half < 2; half++) {
                const int r = row0 + wm * 64 + mt * 16 + gid + half * 8;
                if (r >= M) continue;
                float v0 = acc[mt][nt][half * 2 + 0];
                float v1 = acc[mt][nt][half * 2 + 1];
                if (CMODE == 2) {
                    if (c < N_real) {
                        v0 += __ldg(&bias[c]);
                        if (RELU) v0 = fmaxf(v0, 0.f);
                        c_ext[(size_t)r * N_real + c] = v0;
                    }
                    if (c + 1 < N_real) {
                        v1 += __ldg(&bias[c + 1]);
                        if (RELU) v1 = fmaxf(v1, 0.f);
                        c_ext[(size_t)r * N_real + c + 1] = v1;
                    }
                } else {
                    v0 += __ldg(&bias[c]);
                    v1 += __ldg(&bias[c + 1]);
                    if (RELU) { v0 = fmaxf(v0, 0.f); v1 = fmaxf(v1, 0.f); }
                    if (CMODE == 1) {
                        *reinterpret_cast<float2*>(&g_hf[(size_t)r * N_real + c]) =
                            make_float2(v0, v1);
                    } else {
                        unsigned hi, lo;
                        split2(v0, v1, hi, lo);
                        const size_t o = (size_t)r * (N_real >> 1) + (c >> 1);
                        C0[o] = hi;
                        C1[o] = lo;
                    }
                }
            }
        }
    }
}

// =============================== launch =====================================
extern "C" void kernel_launch(void* const* d_in, const int* in_sizes, int n_in,
                              void* d_out, int out_size)
{
    const float* x  = (const float*)d_in[0];
    const unsigned int* ei = (const unsigned int*)d_in[1];
    const float* W1 = (const float*)d_in[2];
    const float* b1 = (const float*)d_in[3];
    const float* W2 = (const float*)d_in[4];
    const float* b2 = (const float*)d_in[5];
    const float* W3 = (const float*)d_in[6];
    const float* b3 = (const float*)d_in[7];
    const float* W4 = (const float*)d_in[8];
    const float* b4 = (const float*)d_in[9];
    const float* Wl = (const float*)d_in[10];
    const float* bl = (const float*)d_in[11];
    float* out = (float*)d_out;

    const int M = in_sizes[0] / 128;   // 50000
    const int E = in_sizes[1] / 2;     // 800000
    const dim3 blk(256);
    const int nB   = (M + 255) / 256;
    const int eB   = (E + 255) / 256;
    const int aggB = (M * 32 + 255) / 256;
    const int mT   = (M + 127) / 128;

    const int SMB = 2 * 9472 * 4;      // 75776 B (two stages)
    cudaFuncSetAttribute(gemm_bf16<true , 0>, cudaFuncAttributeMaxDynamicSharedMemorySize, SMB);
    cudaFuncSetAttribute(gemm_bf16<true , 1>, cudaFuncAttributeMaxDynamicSharedMemorySize, SMB);
    cudaFuncSetAttribute(gemm_bf16<false, 2>, cudaFuncAttributeMaxDynamicSharedMemorySize, SMB);

    auto pgrid = [&](int k, int nw) { return ((k >> 1) * nw + 255) / 256; };

    // ---- edge index normalize + CSR build (shared by both layers) ----
    detect_idx64 <<<1,  32 >>>(ei);
    convert_idx  <<<eB, blk>>>(ei, E, M);
    zero_deg     <<<nB, blk>>>(M);
    hist_deg     <<<eB, blk>>>(E);
    scan_block   <<<nB, blk>>>(M);
    scan_partials<<<1,  blk>>>(nB);
    scan_add     <<<nB, blk>>>(M, E);
    fill_csr     <<<eB, blk>>>(E);

    // ---- layer 1 (128 -> 128 -> 128) ----
    gin_aggregate_split<<<aggB, blk>>>(x, 1, M);                         // x -> P
    prep_w<<<pgrid(128, 128), blk>>>(W1, 128, 128, 128);
    gemm_bf16<true , 0><<<dim3(1, mT), blk, SMB>>>(0, 1, nullptr, b1, M, 128, 128, 128); // P -> Q
    prep_w<<<pgrid(128, 128), blk>>>(W2, 128, 128, 128);
    gemm_bf16<true , 1><<<dim3(1, mT), blk, SMB>>>(1, 0, nullptr, b2, M, 128, 128, 128); // Q -> g_hf

    // ---- layer 2 (128 -> 256 -> 256) ----
    gin_aggregate_split<<<aggB, blk>>>(nullptr, 0, M);                   // g_hf -> P
    prep_w<<<pgrid(128, 256), blk>>>(W3, 128, 256, 256);
    gemm_bf16<true , 0><<<dim3(2, mT), blk, SMB>>>(0, 1, nullptr, b3, M, 256, 256, 128); // P -> Q
    prep_w<<<pgrid(256, 256), blk>>>(W4, 256, 256, 256);
    gemm_bf16<true , 0><<<dim3(2, mT), blk, SMB>>>(1, 0, nullptr, b4, M, 256, 256, 256); // Q -> P

    // ---- head (256 -> 40, masked in one 128-wide tile) ----
    prep_w<<<pgrid(256, 128), blk>>>(Wl, 256, 40, 128);
    gemm_bf16<false, 2><<<dim3(1, mT), blk, SMB>>>(0, 0, out, bl, M, 40, 128, 256);      // P -> out
}